// round 15
// baseline (speedup 1.0000x reference)
#include <cuda_runtime.h>
#include <cuda_fp16.h>
#include <cstdint>
#include <math.h>

#define T_  1024
#define H_  1024
#define I_  1024
#define E_  16
#define K_  8
#define TK_ (T_ * K_)

// ---------------- scratch (no allocs allowed) ----------------
__device__ int    g_off[E_ + 1];
__device__ int    g_ptok[TK_];
__device__ int    g_pos[TK_];
__device__ int    g_ntiles;
__device__ int    g_tile[96];                        // (e<<16)|row0 per m-tile
__device__ __half q_xh[(size_t)T_ * H_];             // 2 MB
__device__ __half q_gh[(size_t)E_ * 2 * I_ * H_];    // 64 MB
__device__ __half q_dh[(size_t)E_ * H_ * I_];        // 32 MB
__device__ __half g_acth[(size_t)TK_ * I_];          // 16 MB
__device__ float  g_down[(size_t)TK_ * H_];          // 32 MB

// smem: 3-stage cp.async pipeline; per stage A+B fp16 planes, BK=64, 144B pitch
#define PITCHB 144
#define PLB    (128 * PITCHB)    // 18432 B per plane
#define STGB   (2 * PLB)         // 36864 B per stage
#define PIPEB  (3 * STGB)        // 110592 B
#define GSMEM  (PIPEB + 1024)    // + row-index staging (128 ints + pad)

#define NCTA   148               // persistent grid (1 per SM)

__device__ __forceinline__ uint32_t smem_u32(const void* p) {
    uint32_t a;
    asm("{ .reg .u64 t; cvta.to.shared.u64 t, %1; cvt.u32.u64 %0, t; }" : "=r"(a) : "l"(p));
    return a;
}
__device__ __forceinline__ float silu_f(float x) { return x / (1.0f + expf(-x)); }

__device__ __forceinline__ void mma_f16(float* c, const uint32_t* a, const uint32_t* b) {
    asm volatile(
        "mma.sync.aligned.m16n8k16.row.col.f32.f16.f16.f32 "
        "{%0,%1,%2,%3}, {%4,%5,%6,%7}, {%8,%9}, {%0,%1,%2,%3};"
        : "+f"(c[0]), "+f"(c[1]), "+f"(c[2]), "+f"(c[3])
        : "r"(a[0]), "r"(a[1]), "r"(a[2]), "r"(a[3]), "r"(b[0]), "r"(b[1]));
}
__device__ __forceinline__ void ldsm4(uint32_t* d, uint32_t addr) {
    asm volatile("ldmatrix.sync.aligned.m8n8.x4.shared.b16 {%0,%1,%2,%3}, [%4];"
        : "=r"(d[0]), "=r"(d[1]), "=r"(d[2]), "=r"(d[3]) : "r"(addr));
}
__device__ __forceinline__ void cp16(uint32_t dst, const void* src) {
    asm volatile("cp.async.cg.shared.global [%0], [%1], 16;" :: "r"(dst), "l"(src));
}
__device__ __forceinline__ uint32_t h2u(__half2 v) {
    return *reinterpret_cast<uint32_t*>(&v);
}

// ---------------- fp32 -> fp16 pre-pass (pure bandwidth) ----------------
__global__ void cvt_kernel(const float* __restrict__ src, __half* __restrict__ dst) {
    int i = blockIdx.x * 256 + threadIdx.x;
    float4 v = ((const float4*)src)[i];
    uint2 o = make_uint2(h2u(__floats2half2_rn(v.x, v.y)),
                         h2u(__floats2half2_rn(v.z, v.w)));
    ((uint2*)dst)[i] = o;
}

// ---------------- routing + tile-list build ----------------
__global__ void route_kernel(const int* __restrict__ idx) {
    __shared__ int cnt[1024];
    __shared__ int off[1025];
    __shared__ int s_stride;
    int tid = threadIdx.x;
    if (tid == 0) {
        int nz = 0;
        #pragma unroll 1
        for (int j = 1; j < 256; j += 2) nz |= (idx[j] != 0);
        s_stride = nz ? 1 : 2;   // int32 vs int64 payload
    }
    __syncthreads();
    int stride = s_stride;
    int e = tid >> 6, c = tid & 63;
    int j0 = c * 128, j1 = j0 + 128;
    int cn = 0;
    for (int j = j0; j < j1; j++) cn += (idx[j * stride] == e);
    cnt[tid] = cn;
    __syncthreads();
    if (tid == 0) {
        int a = 0;
        for (int i = 0; i < 1024; i++) { off[i] = a; a += cnt[i]; }
        off[1024] = a;
        int t = 0;
        for (int ee = 0; ee < E_; ee++) {
            int b = off[ee * 64], en = off[(ee + 1) * 64];
            g_off[ee] = b;
            for (int r0 = b; r0 < en; r0 += 128) g_tile[t++] = (ee << 16) | r0;
        }
        g_off[E_] = off[1024];
        g_ntiles = t;
    }
    __syncthreads();
    int p = off[tid];
    for (int j = j0; j < j1; j++) {
        if (idx[j * stride] == e) { g_ptok[p] = j >> 3; g_pos[j] = p; p++; }
    }
}

// ---------------------------------------------------------------------------
// Persistent grouped GEMM, 1-pass fp16 mma.sync m16n8k16, BK=64.
// 148 CTAs (1/SM) grid-stride over (m-tile x n-block) work from g_tile[].
// __launch_bounds__(256,1): no 128-reg cap -> no spills in the hot loop.
// Loader: thread -> row (tid>>1), chunks ((tid&1)*4 ..+3) for A and B planes.
// CTA tile 128x128 (FUSE: 128x(64g+64u)), 8 warps (4m x 2n), warp 32x64.
// FUSE=1: A gathered from q_xh, epilogue silu(gate)*up -> g_acth (fp16).
// FUSE=0: A = g_acth, B = q_dh, epilogue -> g_down (fp32).
// ---------------------------------------------------------------------------
template <int FUSE>
__global__ void __launch_bounds__(256, 1)
gemm_f16(const __half* __restrict__ A, const __half* __restrict__ B,
         __half* __restrict__ Dh, float* __restrict__ Df) {
    extern __shared__ char smem[];
    uint32_t sb = smem_u32(smem);
    int* s_arow = (int*)(smem + PIPEB);   // 128 staged A-row indices

    int tid  = threadIdx.x;
    int wid  = tid >> 5;
    int lane = tid & 31;
    int gid  = lane >> 2;
    int tig  = lane & 3;
    int wm   = (wid >> 1) * 32;   // 0,32,64,96
    int wn   = (wid & 1) * 64;    // 0,64

    const int NX = FUSE ? 16 : 8;
    int ntile = g_ntiles;
    int nwork = ntile * NX;

    // ldmatrix lane offsets (layout family verified R10-R13)
    uint32_t aoff = (uint32_t)((((lane >> 3) & 1) * 8 + (lane & 7)) * PITCHB + (lane >> 4) * 16);
    uint32_t boff = (uint32_t)(((lane >> 4) * 8 + (lane & 7)) * PITCHB + ((lane >> 3) & 1) * 16);

    // loader geometry: row = tid>>1 (0..127), chunks (tid&1)*4 .. +3  (8/row total)
    int lrow = tid >> 1;
    int lc4  = (tid & 1) * 4;

    int prev_mt = -1;

    for (int w = blockIdx.x; w < nwork; w += gridDim.x) {
        int mt = w / NX, nx = w - mt * NX;
        int info = g_tile[mt];
        int e    = info >> 16;
        int row0 = info & 0xFFFF;
        int rend = g_off[e + 1];
        int n0   = nx * (FUSE ? 64 : 128);

        // stage A row indices once per new m-tile (pipeline fully drained at tile end)
        if (mt != prev_mt) {
            __syncthreads();
            if (tid < 128) {
                int p = row0 + tid; if (p >= rend) p = rend - 1;
                s_arow[tid] = FUSE ? g_ptok[p] : p;
            }
            __syncthreads();
            prev_mt = mt;
        }

        // per-work-item source bases: one row, 4 chunks each for A and B
        const __half* a0 = A + (size_t)s_arow[lrow] * 1024 + lc4 * 8;
        int br0;
        if (FUSE) br0 = (lrow < 64) ? (n0 + lrow) : (I_ + n0 + lrow - 64);
        else      br0 = n0 + lrow;
        const __half* b0 = B + ((size_t)e * (FUSE ? 2 * I_ : H_) + br0) * 1024 + lc4 * 8;
        uint32_t sd0 = (uint32_t)(lrow * PITCHB + lc4 * 16);

        auto issue = [&](int stg, int it) {
            uint32_t b = sb + stg * STGB;
            int ko = it * 64;   // halves per K-tile
            #pragma unroll
            for (int c = 0; c < 4; c++) {
                cp16(b + sd0 + c * 16,       a0 + ko + c * 8);
                cp16(b + PLB + sd0 + c * 16, b0 + ko + c * 8);
            }
            asm volatile("cp.async.commit_group;" ::: "memory");
        };

        issue(0, 0);
        issue(1, 1);

        float acc[2][8][4];
        #pragma unroll
        for (int m2 = 0; m2 < 2; m2++)
            #pragma unroll
            for (int nt = 0; nt < 8; nt++)
                #pragma unroll
                for (int q = 0; q < 4; q++) acc[m2][nt][q] = 0.f;

        for (int it = 0; it < 16; it++) {
            if (it < 15) asm volatile("cp.async.wait_group 1;" ::: "memory");
            else         asm volatile("cp.async.wait_group 0;" ::: "memory");
            __syncthreads();
            uint32_t bb = sb + (it % 3) * STGB;

            #pragma unroll
            for (int ks = 0; ks < 4; ks++) {
                uint32_t kb = ks * 32;   // 16 halves = 32 B per k16 step
                uint32_t ah[2][4];
                #pragma unroll
                for (int m2 = 0; m2 < 2; m2++)
                    ldsm4(ah[m2], bb + (wm + m2 * 16) * PITCHB + kb + aoff);
                uint32_t bh[8][2];
                #pragma unroll
                for (int np = 0; np < 4; np++) {
                    uint32_t r4[4];
                    ldsm4(r4, bb + PLB + (wn + np * 16) * PITCHB + kb + boff);
                    bh[2*np][0] = r4[0];   bh[2*np][1] = r4[1];
                    bh[2*np+1][0] = r4[2]; bh[2*np+1][1] = r4[3];
                }
                #pragma unroll
                for (int nt = 0; nt < 8; nt++)
                    #pragma unroll
                    for (int m2 = 0; m2 < 2; m2++)
                        mma_f16(acc[m2][nt], ah[m2], bh[nt]);
            }

            if (it + 2 < 16) issue((it + 2) % 3, it + 2);
        }

        if (FUSE) {
            // odd-n warps hold "up" cols; stage fp32, even warps recombine.
            __syncthreads();
            float* s = (float*)smem;   // 128 x 68 fp32 = 34816 B (stages 0-1 reuse)
            if (wid & 1) {
                #pragma unroll
                for (int m2 = 0; m2 < 2; m2++) {
                    int r = wm + m2 * 16 + gid;
                    #pragma unroll
                    for (int nt = 0; nt < 8; nt++) {
                        int c = nt * 8 + 2 * tig;
                        *(float2*)&s[r * 68 + c]       = make_float2(acc[m2][nt][0], acc[m2][nt][1]);
                        *(float2*)&s[(r + 8) * 68 + c] = make_float2(acc[m2][nt][2], acc[m2][nt][3]);
                    }
                }
            }
            __syncthreads();
            if (!(wid & 1)) {
                #pragma unroll
                for (int m2 = 0; m2 < 2; m2++) {
                    int r = wm + m2 * 16 + gid;
                    int p0 = row0 + r, p1 = p0 + 8;
                    #pragma unroll
                    for (int nt = 0; nt < 8; nt++) {
                        int c = nt * 8 + 2 * tig;
                        if (p0 < rend) {
                            float2 u = *(float2*)&s[r * 68 + c];
                            __half2 o = __floats2half2_rn(silu_f(acc[m2][nt][0]) * u.x,
                                                          silu_f(acc[m2][nt][1]) * u.y);
                            *(__half2*)&Dh[(size_t)p0 * I_ + n0 + c] = o;
                        }
                        if (p1 < rend) {
                            float2 u = *(float2*)&s[(r + 8) * 68 + c];
                            __half2 o = __floats2half2_rn(silu_f(acc[m2][nt][2]) * u.x,
                                                          silu_f(acc[m2][nt][3]) * u.y);
                            *(__half2*)&Dh[(size_t)p1 * I_ + n0 + c] = o;
                        }
                    }
                }
            }
            __syncthreads();   // staging reused by next tile's pipeline
        } else {
            #pragma unroll
            for (int m2 = 0; m2 < 2; m2++) {
                int rr0 = row0 + wm + m2 * 16 + gid;
                int rr1 = rr0 + 8;
                #pragma unroll
                for (int nt = 0; nt < 8; nt++) {
                    int cc = n0 + wn + nt * 8 + 2 * tig;
                    if (rr0 < rend)
                        *(float2*)&Df[(size_t)rr0 * H_ + cc] = make_float2(acc[m2][nt][0], acc[m2][nt][1]);
                    if (rr1 < rend)
                        *(float2*)&Df[(size_t)rr1 * H_ + cc] = make_float2(acc[m2][nt][2], acc[m2][nt][3]);
                }
            }
            __syncthreads();   // smem reused by next tile's pipeline
        }
    }
}

// ---------------- combine ----------------
__global__ void combine_kernel(const float* __restrict__ tw, float* __restrict__ out) {
    int t = blockIdx.x;
    __shared__ int   pos[K_];
    __shared__ float w[K_];
    if (threadIdx.x < K_) {
        pos[threadIdx.x] = g_pos[t * K_ + threadIdx.x];
        w[threadIdx.x]   = tw[t * K_ + threadIdx.x];
    }
    __syncthreads();
    int h = 4 * threadIdx.x;
    float4 acc = {0.f, 0.f, 0.f, 0.f};
    #pragma unroll
    for (int k = 0; k < K_; k++) {
        float4 v = *(const float4*)&g_down[(size_t)pos[k] * H_ + h];
        float wk = w[k];
        acc.x += wk * v.x; acc.y += wk * v.y;
        acc.z += wk * v.z; acc.w += wk * v.w;
    }
    *(float4*)&out[(size_t)t * H_ + h] = acc;
}

// ---------------- launch ----------------
extern "C" void kernel_launch(void* const* d_in, const int* in_sizes, int n_in,
                              void* d_out, int out_size) {
    const float* hidden = (const float*)d_in[0];
    const int*   tk_idx = (const int*)d_in[1];
    const float* tk_w   = (const float*)d_in[2];
    const float* gup    = (const float*)d_in[3];
    const float* dproj  = (const float*)d_in[4];
    float*       out    = (float*)d_out;

    __half *xh, *gh, *dh, *acth;
    float  *down_p;
    cudaGetSymbolAddress((void**)&xh,   q_xh);
    cudaGetSymbolAddress((void**)&gh,   q_gh);
    cudaGetSymbolAddress((void**)&dh,   q_dh);
    cudaGetSymbolAddress((void**)&acth, g_acth);
    cudaGetSymbolAddress((void**)&down_p, g_down);

    cudaFuncSetAttribute(gemm_f16<1>, cudaFuncAttributeMaxDynamicSharedMemorySize, GSMEM);
    cudaFuncSetAttribute(gemm_f16<0>, cudaFuncAttributeMaxDynamicSharedMemorySize, GSMEM);

    route_kernel<<<1, 1024>>>(tk_idx);
    cvt_kernel<<<(T_ * H_) / 1024, 256>>>(hidden, xh);
    cvt_kernel<<<(E_ * 2 * I_ * H_) / 1024, 256>>>(gup, gh);
    cvt_kernel<<<(E_ * H_ * I_) / 1024, 256>>>(dproj, dh);

    gemm_f16<1><<<NCTA, 256, GSMEM>>>(xh, gh, acth, nullptr);
    gemm_f16<0><<<NCTA, 256, GSMEM>>>(acth, dh, nullptr, down_p);
    combine_kernel<<<T_, 256>>>(tk_w, out);
}

// round 16
// speedup vs baseline: 1.0898x; 1.0898x over previous
#include <cuda_runtime.h>
#include <cuda_fp16.h>
#include <cstdint>
#include <math.h>

#define T_  1024
#define H_  1024
#define I_  1024
#define E_  16
#define K_  8
#define TK_ (T_ * K_)

// ---------------- scratch (no allocs allowed) ----------------
__device__ int    g_off[E_ + 1];
__device__ int    g_ptok[TK_];
__device__ int    g_pos[TK_];
__device__ int    g_ntiles;
__device__ int    g_tile[96];                        // (e<<16)|row0 per m-tile
__device__ __half q_xh[(size_t)T_ * H_];             // 2 MB
__device__ __half q_gh[(size_t)E_ * 2 * I_ * H_];    // 64 MB
__device__ __half q_dh[(size_t)E_ * H_ * I_];        // 32 MB
__device__ __half g_acth[(size_t)TK_ * I_];          // 16 MB
__device__ float  g_down[(size_t)TK_ * H_];          // 32 MB

// smem: 3-stage cp.async pipeline; per stage A+B fp16 planes, BK=64, 144B pitch
#define PITCHB 144
#define PLB    (128 * PITCHB)    // 18432 B per plane
#define STGB   (2 * PLB)         // 36864 B per stage
#define PIPEB  (3 * STGB)        // 110592 B
#define GSMEM  (PIPEB + 1024)    // + row-index staging; x2 CTAs = 223232 <= 228KB

#define NCTA   296               // persistent grid (2 per SM)

__device__ __forceinline__ uint32_t smem_u32(const void* p) {
    uint32_t a;
    asm("{ .reg .u64 t; cvta.to.shared.u64 t, %1; cvt.u32.u64 %0, t; }" : "=r"(a) : "l"(p));
    return a;
}
__device__ __forceinline__ float silu_f(float x) { return x / (1.0f + expf(-x)); }

__device__ __forceinline__ void mma_f16(float* c, const uint32_t* a, const uint32_t* b) {
    asm volatile(
        "mma.sync.aligned.m16n8k16.row.col.f32.f16.f16.f32 "
        "{%0,%1,%2,%3}, {%4,%5,%6,%7}, {%8,%9}, {%0,%1,%2,%3};"
        : "+f"(c[0]), "+f"(c[1]), "+f"(c[2]), "+f"(c[3])
        : "r"(a[0]), "r"(a[1]), "r"(a[2]), "r"(a[3]), "r"(b[0]), "r"(b[1]));
}
__device__ __forceinline__ void ldsm4(uint32_t* d, uint32_t addr) {
    asm volatile("ldmatrix.sync.aligned.m8n8.x4.shared.b16 {%0,%1,%2,%3}, [%4];"
        : "=r"(d[0]), "=r"(d[1]), "=r"(d[2]), "=r"(d[3]) : "r"(addr));
}
__device__ __forceinline__ void cp16(uint32_t dst, const void* src) {
    asm volatile("cp.async.cg.shared.global [%0], [%1], 16;" :: "r"(dst), "l"(src));
}
__device__ __forceinline__ uint32_t h2u(__half2 v) {
    return *reinterpret_cast<uint32_t*>(&v);
}

// ---------------- fp32 -> fp16 pre-pass (pure bandwidth) ----------------
__global__ void cvt_kernel(const float* __restrict__ src, __half* __restrict__ dst) {
    int i = blockIdx.x * 256 + threadIdx.x;
    float4 v = ((const float4*)src)[i];
    uint2 o = make_uint2(h2u(__floats2half2_rn(v.x, v.y)),
                         h2u(__floats2half2_rn(v.z, v.w)));
    ((uint2*)dst)[i] = o;
}

// ---------------- routing + tile-list build ----------------
__global__ void route_kernel(const int* __restrict__ idx) {
    __shared__ int cnt[1024];
    __shared__ int off[1025];
    __shared__ int s_stride;
    int tid = threadIdx.x;
    if (tid == 0) {
        int nz = 0;
        #pragma unroll 1
        for (int j = 1; j < 256; j += 2) nz |= (idx[j] != 0);
        s_stride = nz ? 1 : 2;   // int32 vs int64 payload
    }
    __syncthreads();
    int stride = s_stride;
    int e = tid >> 6, c = tid & 63;
    int j0 = c * 128, j1 = j0 + 128;
    int cn = 0;
    for (int j = j0; j < j1; j++) cn += (idx[j * stride] == e);
    cnt[tid] = cn;
    __syncthreads();
    if (tid == 0) {
        int a = 0;
        for (int i = 0; i < 1024; i++) { off[i] = a; a += cnt[i]; }
        off[1024] = a;
        int t = 0;
        for (int ee = 0; ee < E_; ee++) {
            int b = off[ee * 64], en = off[(ee + 1) * 64];
            g_off[ee] = b;
            for (int r0 = b; r0 < en; r0 += 128) g_tile[t++] = (ee << 16) | r0;
        }
        g_off[E_] = off[1024];
        g_ntiles = t;
    }
    __syncthreads();
    int p = off[tid];
    for (int j = j0; j < j1; j++) {
        if (idx[j * stride] == e) { g_ptok[p] = j >> 3; g_pos[j] = p; p++; }
    }
}

// ---------------------------------------------------------------------------
// Persistent grouped GEMM, 1-pass fp16 mma.sync m16n8k16, BK=64.
// 296 CTAs (2/SM) grid-stride over (m-tile x n-block) work from g_tile[].
// Slim loader (1 row/thread via smem-staged indices) -> ~112 regs, no spill @cap128.
// CTA tile 128x128 (FUSE: 128x(64g+64u)), 8 warps (4m x 2n), warp 32x64.
// FUSE=1: A gathered from q_xh, epilogue silu(gate)*up -> g_acth (fp16).
// FUSE=0: A = g_acth, B = q_dh, epilogue -> g_down (fp32).
// ---------------------------------------------------------------------------
template <int FUSE>
__global__ void __launch_bounds__(256, 2)
gemm_f16(const __half* __restrict__ A, const __half* __restrict__ B,
         __half* __restrict__ Dh, float* __restrict__ Df) {
    extern __shared__ char smem[];
    uint32_t sb = smem_u32(smem);
    int* s_arow = (int*)(smem + PIPEB);   // 128 staged A-row indices

    int tid  = threadIdx.x;
    int wid  = tid >> 5;
    int lane = tid & 31;
    int gid  = lane >> 2;
    int tig  = lane & 3;
    int wm   = (wid >> 1) * 32;   // 0,32,64,96
    int wn   = (wid & 1) * 64;    // 0,64

    const int NX = FUSE ? 16 : 8;
    int nwork = g_ntiles * NX;

    // ldmatrix lane offsets (layout family verified R10-R15)
    uint32_t aoff = (uint32_t)((((lane >> 3) & 1) * 8 + (lane & 7)) * PITCHB + (lane >> 4) * 16);
    uint32_t boff = (uint32_t)(((lane >> 4) * 8 + (lane & 7)) * PITCHB + ((lane >> 3) & 1) * 16);

    // loader geometry: row = tid>>1 (0..127), chunks (tid&1)*4 .. +3  (8/row total)
    int lrow = tid >> 1;
    int lc4  = (tid & 1) * 4;

    for (int w = blockIdx.x; w < nwork; w += gridDim.x) {
        int mt = w / NX, nx = w - mt * NX;
        int info = g_tile[mt];
        int e    = info >> 16;
        int row0 = info & 0xFFFF;
        int rend = g_off[e + 1];
        int n0   = nx * (FUSE ? 64 : 128);

        // stage A row indices (pipeline fully drained at previous tile end)
        __syncthreads();
        if (tid < 128) {
            int p = row0 + tid; if (p >= rend) p = rend - 1;
            s_arow[tid] = FUSE ? g_ptok[p] : p;
        }
        __syncthreads();

        // per-work-item source bases: one row, 4 chunks each for A and B
        const __half* a0 = A + (size_t)s_arow[lrow] * 1024 + lc4 * 8;
        int br0;
        if (FUSE) br0 = (lrow < 64) ? (n0 + lrow) : (I_ + n0 + lrow - 64);
        else      br0 = n0 + lrow;
        const __half* b0 = B + ((size_t)e * (FUSE ? 2 * I_ : H_) + br0) * 1024 + lc4 * 8;
        uint32_t sd0 = (uint32_t)(lrow * PITCHB + lc4 * 16);

        auto issue = [&](int stg, int it) {
            uint32_t b = sb + stg * STGB;
            int ko = it * 64;   // halves per K-tile
            #pragma unroll
            for (int c = 0; c < 4; c++) {
                cp16(b + sd0 + c * 16,       a0 + ko + c * 8);
                cp16(b + PLB + sd0 + c * 16, b0 + ko + c * 8);
            }
            asm volatile("cp.async.commit_group;" ::: "memory");
        };

        issue(0, 0);
        issue(1, 1);

        float acc[2][8][4];
        #pragma unroll
        for (int m2 = 0; m2 < 2; m2++)
            #pragma unroll
            for (int nt = 0; nt < 8; nt++)
                #pragma unroll
                for (int q = 0; q < 4; q++) acc[m2][nt][q] = 0.f;

        for (int it = 0; it < 16; it++) {
            if (it < 15) asm volatile("cp.async.wait_group 1;" ::: "memory");
            else         asm volatile("cp.async.wait_group 0;" ::: "memory");
            __syncthreads();
            uint32_t bb = sb + (it % 3) * STGB;

            #pragma unroll
            for (int ks = 0; ks < 4; ks++) {
                uint32_t kb = ks * 32;   // 16 halves = 32 B per k16 step
                uint32_t ah[2][4];
                #pragma unroll
                for (int m2 = 0; m2 < 2; m2++)
                    ldsm4(ah[m2], bb + (wm + m2 * 16) * PITCHB + kb + aoff);
                uint32_t bh[8][2];
                #pragma unroll
                for (int np = 0; np < 4; np++) {
                    uint32_t r4[4];
                    ldsm4(r4, bb + PLB + (wn + np * 16) * PITCHB + kb + boff);
                    bh[2*np][0] = r4[0];   bh[2*np][1] = r4[1];
                    bh[2*np+1][0] = r4[2]; bh[2*np+1][1] = r4[3];
                }
                #pragma unroll
                for (int nt = 0; nt < 8; nt++)
                    #pragma unroll
                    for (int m2 = 0; m2 < 2; m2++)
                        mma_f16(acc[m2][nt], ah[m2], bh[nt]);
            }

            if (it + 2 < 16) issue((it + 2) % 3, it + 2);
        }

        if (FUSE) {
            // odd-n warps hold "up" cols; stage fp32, even warps recombine.
            __syncthreads();
            float* s = (float*)smem;   // 128 x 68 fp32 = 34816 B (stages 0-1 reuse)
            if (wid & 1) {
                #pragma unroll
                for (int m2 = 0; m2 < 2; m2++) {
                    int r = wm + m2 * 16 + gid;
                    #pragma unroll
                    for (int nt = 0; nt < 8; nt++) {
                        int c = nt * 8 + 2 * tig;
                        *(float2*)&s[r * 68 + c]       = make_float2(acc[m2][nt][0], acc[m2][nt][1]);
                        *(float2*)&s[(r + 8) * 68 + c] = make_float2(acc[m2][nt][2], acc[m2][nt][3]);
                    }
                }
            }
            __syncthreads();
            if (!(wid & 1)) {
                #pragma unroll
                for (int m2 = 0; m2 < 2; m2++) {
                    int r = wm + m2 * 16 + gid;
                    int p0 = row0 + r, p1 = p0 + 8;
                    #pragma unroll
                    for (int nt = 0; nt < 8; nt++) {
                        int c = nt * 8 + 2 * tig;
                        if (p0 < rend) {
                            float2 u = *(float2*)&s[r * 68 + c];
                            __half2 o = __floats2half2_rn(silu_f(acc[m2][nt][0]) * u.x,
                                                          silu_f(acc[m2][nt][1]) * u.y);
                            *(__half2*)&Dh[(size_t)p0 * I_ + n0 + c] = o;
                        }
                        if (p1 < rend) {
                            float2 u = *(float2*)&s[(r + 8) * 68 + c];
                            __half2 o = __floats2half2_rn(silu_f(acc[m2][nt][2]) * u.x,
                                                          silu_f(acc[m2][nt][3]) * u.y);
                            *(__half2*)&Dh[(size_t)p1 * I_ + n0 + c] = o;
                        }
                    }
                }
            }
        } else {
            #pragma unroll
            for (int m2 = 0; m2 < 2; m2++) {
                int rr0 = row0 + wm + m2 * 16 + gid;
                int rr1 = rr0 + 8;
                #pragma unroll
                for (int nt = 0; nt < 8; nt++) {
                    int cc = n0 + wn + nt * 8 + 2 * tig;
                    if (rr0 < rend)
                        *(float2*)&Df[(size_t)rr0 * H_ + cc] = make_float2(acc[m2][nt][0], acc[m2][nt][1]);
                    if (rr1 < rend)
                        *(float2*)&Df[(size_t)rr1 * H_ + cc] = make_float2(acc[m2][nt][2], acc[m2][nt][3]);
                }
            }
        }
    }
}

// ---------------- combine ----------------
__global__ void combine_kernel(const float* __restrict__ tw, float* __restrict__ out) {
    int t = blockIdx.x;
    __shared__ int   pos[K_];
    __shared__ float w[K_];
    if (threadIdx.x < K_) {
        pos[threadIdx.x] = g_pos[t * K_ + threadIdx.x];
        w[threadIdx.x]   = tw[t * K_ + threadIdx.x];
    }
    __syncthreads();
    int h = 4 * threadIdx.x;
    float4 acc = {0.f, 0.f, 0.f, 0.f};
    #pragma unroll
    for (int k = 0; k < K_; k++) {
        float4 v = *(const float4*)&g_down[(size_t)pos[k] * H_ + h];
        float wk = w[k];
        acc.x += wk * v.x; acc.y += wk * v.y;
        acc.z += wk * v.z; acc.w += wk * v.w;
    }
    *(float4*)&out[(size_t)t * H_ + h] = acc;
}

// ---------------- launch ----------------
extern "C" void kernel_launch(void* const* d_in, const int* in_sizes, int n_in,
                              void* d_out, int out_size) {
    const float* hidden = (const float*)d_in[0];
    const int*   tk_idx = (const int*)d_in[1];
    const float* tk_w   = (const float*)d_in[2];
    const float* gup    = (const float*)d_in[3];
    const float* dproj  = (const float*)d_in[4];
    float*       out    = (float*)d_out;

    __half *xh, *gh, *dh, *acth;
    float  *down_p;
    cudaGetSymbolAddress((void**)&xh,   q_xh);
    cudaGetSymbolAddress((void**)&gh,   q_gh);
    cudaGetSymbolAddress((void**)&dh,   q_dh);
    cudaGetSymbolAddress((void**)&acth, g_acth);
    cudaGetSymbolAddress((void**)&down_p, g_down);

    cudaFuncSetAttribute(gemm_f16<1>, cudaFuncAttributeMaxDynamicSharedMemorySize, GSMEM);
    cudaFuncSetAttribute(gemm_f16<0>, cudaFuncAttributeMaxDynamicSharedMemorySize, GSMEM);

    route_kernel<<<1, 1024>>>(tk_idx);
    cvt_kernel<<<(T_ * H_) / 1024, 256>>>(hidden, xh);
    cvt_kernel<<<(E_ * 2 * I_ * H_) / 1024, 256>>>(gup, gh);
    cvt_kernel<<<(E_ * H_ * I_) / 1024, 256>>>(dproj, dh);

    gemm_f16<1><<<NCTA, 256, GSMEM>>>(xh, gh, acth, nullptr);
    gemm_f16<0><<<NCTA, 256, GSMEM>>>(acth, dh, nullptr, down_p);
    combine_kernel<<<T_, 256>>>(tk_w, out);
}

// round 17
// speedup vs baseline: 1.3549x; 1.2433x over previous
#include <cuda_runtime.h>
#include <cuda_fp16.h>
#include <cstdint>
#include <math.h>

#define T_  1024
#define H_  1024
#define I_  1024
#define E_  16
#define K_  8
#define TK_ (T_ * K_)

// ---------------- scratch (no allocs allowed) ----------------
__device__ int    g_off[E_ + 1];
__device__ int    g_ptok[TK_];
__device__ int    g_pos[TK_];
__device__ int    g_ntiles;
__device__ int    g_tile[96];                        // (e<<16)|row0 per m-tile
__device__ __half q_xh[(size_t)T_ * H_];             // 2 MB
__device__ __half q_gh[(size_t)E_ * 2 * I_ * H_];    // 64 MB
__device__ __half q_dh[(size_t)E_ * H_ * I_];        // 32 MB
__device__ __half g_acth[(size_t)TK_ * I_];          // 16 MB
__device__ float  g_down[(size_t)TK_ * H_];          // 32 MB

// smem: 3-stage cp.async pipeline; per stage A+B fp16 planes, BK=64, 144B pitch
#define PITCHB 144
#define PLB    (128 * PITCHB)    // 18432 B per plane
#define STGB   (2 * PLB)         // 36864 B per stage
#define PIPEB  (3 * STGB)        // 110592 B
#define GSMEM  PIPEB

#define NCTA   148               // persistent grid (1 per SM; ~148 regs/thread)

__device__ __forceinline__ uint32_t smem_u32(const void* p) {
    uint32_t a;
    asm("{ .reg .u64 t; cvta.to.shared.u64 t, %1; cvt.u32.u64 %0, t; }" : "=r"(a) : "l"(p));
    return a;
}
__device__ __forceinline__ float silu_f(float x) { return x / (1.0f + expf(-x)); }

__device__ __forceinline__ void mma_f16(float* c, const uint32_t* a, const uint32_t* b) {
    asm volatile(
        "mma.sync.aligned.m16n8k16.row.col.f32.f16.f16.f32 "
        "{%0,%1,%2,%3}, {%4,%5,%6,%7}, {%8,%9}, {%0,%1,%2,%3};"
        : "+f"(c[0]), "+f"(c[1]), "+f"(c[2]), "+f"(c[3])
        : "r"(a[0]), "r"(a[1]), "r"(a[2]), "r"(a[3]), "r"(b[0]), "r"(b[1]));
}
__device__ __forceinline__ void ldsm4(uint32_t* d, uint32_t addr) {
    asm volatile("ldmatrix.sync.aligned.m8n8.x4.shared.b16 {%0,%1,%2,%3}, [%4];"
        : "=r"(d[0]), "=r"(d[1]), "=r"(d[2]), "=r"(d[3]) : "r"(addr));
}
__device__ __forceinline__ void cp16(uint32_t dst, const void* src) {
    asm volatile("cp.async.cg.shared.global [%0], [%1], 16;" :: "r"(dst), "l"(src));
}
__device__ __forceinline__ uint32_t h2u(__half2 v) {
    return *reinterpret_cast<uint32_t*>(&v);
}

// ---------------- fp32 -> fp16 pre-pass (pure bandwidth) ----------------
__global__ void cvt_kernel(const float* __restrict__ src, __half* __restrict__ dst) {
    int i = blockIdx.x * 256 + threadIdx.x;
    float4 v = ((const float4*)src)[i];
    uint2 o = make_uint2(h2u(__floats2half2_rn(v.x, v.y)),
                         h2u(__floats2half2_rn(v.z, v.w)));
    ((uint2*)dst)[i] = o;
}

// ---------------- routing + tile-list build ----------------
__global__ void route_kernel(const int* __restrict__ idx) {
    __shared__ int cnt[1024];
    __shared__ int off[1025];
    __shared__ int s_stride;
    int tid = threadIdx.x;
    if (tid == 0) {
        int nz = 0;
        #pragma unroll 1
        for (int j = 1; j < 256; j += 2) nz |= (idx[j] != 0);
        s_stride = nz ? 1 : 2;   // int32 vs int64 payload
    }
    __syncthreads();
    int stride = s_stride;
    int e = tid >> 6, c = tid & 63;
    int j0 = c * 128, j1 = j0 + 128;
    int cn = 0;
    for (int j = j0; j < j1; j++) cn += (idx[j * stride] == e);
    cnt[tid] = cn;
    __syncthreads();
    if (tid == 0) {
        int a = 0;
        for (int i = 0; i < 1024; i++) { off[i] = a; a += cnt[i]; }
        off[1024] = a;
        int t = 0;
        for (int ee = 0; ee < E_; ee++) {
            int b = off[ee * 64], en = off[(ee + 1) * 64];
            g_off[ee] = b;
            for (int r0 = b; r0 < en; r0 += 128) g_tile[t++] = (ee << 16) | r0;
        }
        g_off[E_] = off[1024];
        g_ntiles = t;
    }
    __syncthreads();
    int p = off[tid];
    for (int j = j0; j < j1; j++) {
        if (idx[j * stride] == e) { g_ptok[p] = j >> 3; g_pos[j] = p; p++; }
    }
}

// ---------------------------------------------------------------------------
// Persistent grouped GEMM, 1-pass fp16 mma.sync m16n8k16, BK=64.
// 148 CTAs (1/SM, occ1 -> ~148 regs, no spill) grid-stride over work items.
// R13 coalesced loader (warp = 4 full 128B rows per cp.async instruction).
// Register double-buffered ldmatrix fragments: ks+1 LDSM issued before ks MMAs.
// CTA tile 128x128 (FUSE: 128x(64g+64u)), 8 warps (4m x 2n), warp 32x64.
// FUSE=1: A gathered from q_xh, epilogue silu(gate)*up -> g_acth (fp16).
// FUSE=0: A = g_acth, B = q_dh, epilogue -> g_down (fp32).
// ---------------------------------------------------------------------------
template <int FUSE>
__global__ void __launch_bounds__(256, 1)
gemm_f16(const __half* __restrict__ A, const __half* __restrict__ B,
         __half* __restrict__ Dh, float* __restrict__ Df) {
    extern __shared__ char smem[];
    uint32_t sb = smem_u32(smem);

    int tid  = threadIdx.x;
    int wid  = tid >> 5;
    int lane = tid & 31;
    int gid  = lane >> 2;
    int tig  = lane & 3;
    int wm   = (wid >> 1) * 32;   // 0,32,64,96
    int wn   = (wid & 1) * 64;    // 0,64

    const int NX = FUSE ? 16 : 8;
    int nwork = g_ntiles * NX;

    // ldmatrix lane offsets (layout family verified R10-R16)
    uint32_t aoff = (uint32_t)((((lane >> 3) & 1) * 8 + (lane & 7)) * PITCHB + (lane >> 4) * 16);
    uint32_t boff = (uint32_t)(((lane >> 4) * 8 + (lane & 7)) * PITCHB + ((lane >> 3) & 1) * 16);

    for (int w = blockIdx.x; w < nwork; w += gridDim.x) {
        int mt = w / NX, nx = w - mt * NX;
        int info = g_tile[mt];
        int e    = info >> 16;
        int row0 = info & 0xFFFF;
        int rend = g_off[e + 1];
        int n0   = nx * (FUSE ? 64 : 128);

        // R13 coalesced loader mapping: 4 rows (u=tid+256j), all 8 chunks per warp
        const __half* asrc[4];
        const __half* bsrc[4];
        uint32_t sa[4];
        #pragma unroll
        for (int j = 0; j < 4; j++) {
            int u = tid + 256 * j;        // 0..1023
            int r = u >> 3, c = u & 7;    // row, 16B-chunk
            int p = row0 + r; if (p >= rend) p = rend - 1;
            size_t arow = FUSE ? (size_t)g_ptok[p] : (size_t)p;
            asrc[j] = A + arow * 1024 + c * 8;
            int br;
            if (FUSE) br = (r < 64) ? (n0 + r) : (I_ + n0 + r - 64);
            else      br = n0 + r;
            bsrc[j] = B + ((size_t)e * (FUSE ? 2 * I_ : H_) + br) * 1024 + c * 8;
            sa[j] = (uint32_t)(r * PITCHB + c * 16);
        }

        auto issue = [&](int stg, int it) {
            uint32_t b = sb + stg * STGB;
            int ko = it * 64;   // halves per K-tile
            #pragma unroll
            for (int j = 0; j < 4; j++) cp16(b + sa[j], asrc[j] + ko);
            #pragma unroll
            for (int j = 0; j < 4; j++) cp16(b + PLB + sa[j], bsrc[j] + ko);
            asm volatile("cp.async.commit_group;" ::: "memory");
        };

        issue(0, 0);
        issue(1, 1);

        float acc[2][8][4];
        #pragma unroll
        for (int m2 = 0; m2 < 2; m2++)
            #pragma unroll
            for (int nt = 0; nt < 8; nt++)
                #pragma unroll
                for (int q = 0; q < 4; q++) acc[m2][nt][q] = 0.f;

        // double-buffered fragment registers
        uint32_t ah[2][2][4];
        uint32_t bh[2][8][2];

        auto load_frags = [&](uint32_t bb, int ks, int pb) {
            uint32_t kb = (uint32_t)ks * 32;   // 16 halves = 32 B per k16 step
            #pragma unroll
            for (int m2 = 0; m2 < 2; m2++)
                ldsm4(ah[pb][m2], bb + (wm + m2 * 16) * PITCHB + kb + aoff);
            #pragma unroll
            for (int np = 0; np < 4; np++) {
                uint32_t r4[4];
                ldsm4(r4, bb + PLB + (wn + np * 16) * PITCHB + kb + boff);
                bh[pb][2*np][0] = r4[0];   bh[pb][2*np][1] = r4[1];
                bh[pb][2*np+1][0] = r4[2]; bh[pb][2*np+1][1] = r4[3];
            }
        };

        for (int it = 0; it < 16; it++) {
            if (it < 15) asm volatile("cp.async.wait_group 1;" ::: "memory");
            else         asm volatile("cp.async.wait_group 0;" ::: "memory");
            __syncthreads();
            uint32_t bb = sb + (it % 3) * STGB;

            if (it + 2 < 16) issue((it + 2) % 3, it + 2);   // overlap whole iter

            load_frags(bb, 0, 0);
            #pragma unroll
            for (int ks = 0; ks < 4; ks++) {
                int cur = ks & 1;
                if (ks < 3) load_frags(bb, ks + 1, cur ^ 1);  // hide LDSM under MMAs
                #pragma unroll
                for (int nt = 0; nt < 8; nt++)
                    #pragma unroll
                    for (int m2 = 0; m2 < 2; m2++)
                        mma_f16(acc[m2][nt], ah[cur][m2], bh[cur][nt]);
            }
        }

        if (FUSE) {
            // odd-n warps hold "up" cols; stage fp32, even warps recombine.
            __syncthreads();
            float* s = (float*)smem;   // 128 x 68 fp32 = 34816 B (stage 0 reuse)
            if (wid & 1) {
                #pragma unroll
                for (int m2 = 0; m2 < 2; m2++) {
                    int r = wm + m2 * 16 + gid;
                    #pragma unroll
                    for (int nt = 0; nt < 8; nt++) {
                        int c = nt * 8 + 2 * tig;
                        *(float2*)&s[r * 68 + c]       = make_float2(acc[m2][nt][0], acc[m2][nt][1]);
                        *(float2*)&s[(r + 8) * 68 + c] = make_float2(acc[m2][nt][2], acc[m2][nt][3]);
                    }
                }
            }
            __syncthreads();
            if (!(wid & 1)) {
                #pragma unroll
                for (int m2 = 0; m2 < 2; m2++) {
                    int r = wm + m2 * 16 + gid;
                    int p0 = row0 + r, p1 = p0 + 8;
                    #pragma unroll
                    for (int nt = 0; nt < 8; nt++) {
                        int c = nt * 8 + 2 * tig;
                        if (p0 < rend) {
                            float2 u = *(float2*)&s[r * 68 + c];
                            __half2 o = __floats2half2_rn(silu_f(acc[m2][nt][0]) * u.x,
                                                          silu_f(acc[m2][nt][1]) * u.y);
                            *(__half2*)&Dh[(size_t)p0 * I_ + n0 + c] = o;
                        }
                        if (p1 < rend) {
                            float2 u = *(float2*)&s[(r + 8) * 68 + c];
                            __half2 o = __floats2half2_rn(silu_f(acc[m2][nt][2]) * u.x,
                                                          silu_f(acc[m2][nt][3]) * u.y);
                            *(__half2*)&Dh[(size_t)p1 * I_ + n0 + c] = o;
                        }
                    }
                }
            }
            __syncthreads();   // staging reused by next tile's pipeline
        } else {
            #pragma unroll
            for (int m2 = 0; m2 < 2; m2++) {
                int rr0 = row0 + wm + m2 * 16 + gid;
                int rr1 = rr0 + 8;
                #pragma unroll
                for (int nt = 0; nt < 8; nt++) {
                    int cc = n0 + wn + nt * 8 + 2 * tig;
                    if (rr0 < rend)
                        *(float2*)&Df[(size_t)rr0 * H_ + cc] = make_float2(acc[m2][nt][0], acc[m2][nt][1]);
                    if (rr1 < rend)
                        *(float2*)&Df[(size_t)rr1 * H_ + cc] = make_float2(acc[m2][nt][2], acc[m2][nt][3]);
                }
            }
            __syncthreads();   // smem reused by next tile's pipeline
        }
    }
}

// ---------------- combine ----------------
__global__ void combine_kernel(const float* __restrict__ tw, float* __restrict__ out) {
    int t = blockIdx.x;
    __shared__ int   pos[K_];
    __shared__ float w[K_];
    if (threadIdx.x < K_) {
        pos[threadIdx.x] = g_pos[t * K_ + threadIdx.x];
        w[threadIdx.x]   = tw[t * K_ + threadIdx.x];
    }
    __syncthreads();
    int h = 4 * threadIdx.x;
    float4 acc = {0.f, 0.f, 0.f, 0.f};
    #pragma unroll
    for (int k = 0; k < K_; k++) {
        float4 v = *(const float4*)&g_down[(size_t)pos[k] * H_ + h];
        float wk = w[k];
        acc.x += wk * v.x; acc.y += wk * v.y;
        acc.z += wk * v.z; acc.w += wk * v.w;
    }
    *(float4*)&out[(size_t)t * H_ + h] = acc;
}

// ---------------- launch ----------------
extern "C" void kernel_launch(void* const* d_in, const int* in_sizes, int n_in,
                              void* d_out, int out_size) {
    const float* hidden = (const float*)d_in[0];
    const int*   tk_idx = (const int*)d_in[1];
    const float* tk_w   = (const float*)d_in[2];
    const float* gup    = (const float*)d_in[3];
    const float* dproj  = (const float*)d_in[4];
    float*       out    = (float*)d_out;

    __half *xh, *gh, *dh, *acth;
    float  *down_p;
    cudaGetSymbolAddress((void**)&xh,   q_xh);
    cudaGetSymbolAddress((void**)&gh,   q_gh);
    cudaGetSymbolAddress((void**)&dh,   q_dh);
    cudaGetSymbolAddress((void**)&acth, g_acth);
    cudaGetSymbolAddress((void**)&down_p, g_down);

    cudaFuncSetAttribute(gemm_f16<1>, cudaFuncAttributeMaxDynamicSharedMemorySize, GSMEM);
    cudaFuncSetAttribute(gemm_f16<0>, cudaFuncAttributeMaxDynamicSharedMemorySize, GSMEM);

    route_kernel<<<1, 1024>>>(tk_idx);
    cvt_kernel<<<(T_ * H_) / 1024, 256>>>(hidden, xh);
    cvt_kernel<<<(E_ * 2 * I_ * H_) / 1024, 256>>>(gup, gh);
    cvt_kernel<<<(E_ * H_ * I_) / 1024, 256>>>(dproj, dh);

    gemm_f16<1><<<NCTA, 256, GSMEM>>>(xh, gh, acth, nullptr);
    gemm_f16<0><<<NCTA, 256, GSMEM>>>(acth, dh, nullptr, down_p);
    combine_kernel<<<T_, 256>>>(tk_w, out);
}